// round 6
// baseline (speedup 1.0000x reference)
#include <cuda_runtime.h>
#include <math.h>

// Problem constants
#define Bb   32
#define Ss   1024
#define Hh   256
#define Pp   96
#define Ll   200
#define Oo   200
#define Ee   64
#define Mtot (Bb*Ss)   // 32768

typedef unsigned long long u64;

__device__ __forceinline__ u64 pack2(float x, float y) {
    u64 r; asm("mov.b64 %0, {%1, %2};" : "=l"(r) : "f"(x), "f"(y)); return r;
}
__device__ __forceinline__ void unpack2(u64 v, float& x, float& y) {
    asm("mov.b64 {%0, %1}, %2;" : "=f"(x), "=f"(y) : "l"(v));
}
__device__ __forceinline__ void ffma2(u64& acc, u64 a, u64 b) {
    asm("fma.rn.f32x2 %0, %1, %2, %0;" : "+l"(acc) : "l"(a), "l"(b));
}

// Scratch
__device__ float g_h  [3u*Mtot*Ll];
__device__ float g_hid[3u*Mtot*Ll];
__device__ float g_qkv[3u*Mtot*Hh];
__device__ float g_ctx[(unsigned)Mtot*Hh];
__device__ float g_eco[Bb*Hh];

// ---------------------------------------------------------------------------
__global__ void eco_kernel(const float* __restrict__ eco_data,
                           const float* __restrict__ W_eco,
                           const float* __restrict__ b_eco,
                           float* __restrict__ out)
{
    int b = blockIdx.x;
    int h = threadIdx.x;
    float acc = b_eco[h];
    #pragma unroll 8
    for (int e = 0; e < Ee; e++)
        acc = fmaf(eco_data[b*Ee + e], W_eco[e*Hh + h], acc);
    out[b*Hh + h] = acc;
}

// ---------------------------------------------------------------------------
// FFMA2 tiled GEMM: C[M,N] = A[M,K] @ W[K,N], 64x64 tile, 256 threads,
// thread tile 2 rows x 8 cols (4 f32x2 pairs), double-buffered smem.
// M must be a multiple of 64 (always true here).
// MODE 0: h-init   C = tanh(acc + timef[row]*Wt[col] + bias[col])
// MODE 1: hid      C = tanh(acc + bias[col])
// MODE 2: update   C += 0.25*(acc + bias[col])
// MODE 3: qkv      C = mask(row) * (acc + bias[col] + eco[b(row)][col])
// MODE 4: head     C = acc + bias[col]
// ---------------------------------------------------------------------------
template<int MODE>
__global__ __launch_bounds__(256)
void gemm_kernel(const float* __restrict__ A, const float* __restrict__ W,
                 float* __restrict__ C,
                 int M, int N, int K,
                 long aStride, long wStride, long cStride, int biasStride,
                 const float* __restrict__ bias,
                 const float* __restrict__ aux1,
                 const float* __restrict__ aux2, int aux2Stride)
{
    int kb = blockIdx.z;
    A += (long)kb * aStride;
    W += (long)kb * wStride;
    C += (long)kb * cStride;
    const float* bptr = bias + (long)kb * biasStride;
    const float* a2   = aux2 ? (aux2 + (long)kb * aux2Stride) : nullptr;

    __shared__ __align__(16) float As[2][64][17];
    __shared__ __align__(16) float Ws[2][16][72];

    int tid = threadIdx.x;
    int tx = tid & 7;          // 8 groups -> 8 cols each
    int ty = tid >> 3;         // 32 groups -> 2 rows each
    int m0 = blockIdx.x * 64, n0 = blockIdx.y * 64;
    int row0 = ty*2, row1 = row0 + 1;

    // load-index precompute
    int aR = tid >> 4, aC = tid & 15;       // A panel: 64x16
    int wR = tid >> 6, wC = tid & 63;       // W panel: 16x64

    int P = (K + 15) >> 4;
    float ar[4], wr[4];

    // preload panel 0
    {
        int k0 = 0;
        #pragma unroll
        for (int i = 0; i < 4; i++) {
            int gc = k0 + aC;
            ar[i] = (gc < K) ? A[(long)(m0 + aR + 16*i)*K + gc] : 0.f;
        }
        #pragma unroll
        for (int i = 0; i < 4; i++) {
            int gr = k0 + wR + 4*i;
            int gc = n0 + wC;
            wr[i] = (gr < K && gc < N) ? W[(long)gr*N + gc] : 0.f;
        }
        #pragma unroll
        for (int i = 0; i < 4; i++) As[0][aR + 16*i][aC] = ar[i];
        #pragma unroll
        for (int i = 0; i < 4; i++) Ws[0][wR + 4*i][wC] = wr[i];
    }
    __syncthreads();

    u64 acc[2][4];
    #pragma unroll
    for (int i = 0; i < 2; i++)
        #pragma unroll
        for (int j = 0; j < 4; j++) acc[i][j] = 0ull;

    for (int p = 0; p < P; p++) {
        int cur = p & 1, nxt = cur ^ 1;
        if (p + 1 < P) {
            int k0 = (p + 1) << 4;
            #pragma unroll
            for (int i = 0; i < 4; i++) {
                int gc = k0 + aC;
                ar[i] = (gc < K) ? A[(long)(m0 + aR + 16*i)*K + gc] : 0.f;
            }
            #pragma unroll
            for (int i = 0; i < 4; i++) {
                int gr = k0 + wR + 4*i;
                int gc = n0 + wC;
                wr[i] = (gr < K && gc < N) ? W[(long)gr*N + gc] : 0.f;
            }
        }
        #pragma unroll
        for (int kk = 0; kk < 16; kk++) {
            ulonglong2 b01 = *(const ulonglong2*)&Ws[cur][kk][tx*8];
            ulonglong2 b23 = *(const ulonglong2*)&Ws[cur][kk][tx*8 + 4];
            float a0 = As[cur][row0][kk];
            float a1 = As[cur][row1][kk];
            u64 ap0 = pack2(a0, a0);
            u64 ap1 = pack2(a1, a1);
            ffma2(acc[0][0], ap0, b01.x); ffma2(acc[0][1], ap0, b01.y);
            ffma2(acc[0][2], ap0, b23.x); ffma2(acc[0][3], ap0, b23.y);
            ffma2(acc[1][0], ap1, b01.x); ffma2(acc[1][1], ap1, b01.y);
            ffma2(acc[1][2], ap1, b23.x); ffma2(acc[1][3], ap1, b23.y);
        }
        if (p + 1 < P) {
            #pragma unroll
            for (int i = 0; i < 4; i++) As[nxt][aR + 16*i][aC] = ar[i];
            #pragma unroll
            for (int i = 0; i < 4; i++) Ws[nxt][wR + 4*i][wC] = wr[i];
        }
        __syncthreads();
    }

    // epilogue
    #pragma unroll
    for (int i = 0; i < 2; i++) {
        int row = m0 + ty*2 + i;
        float vals[8];
        #pragma unroll
        for (int jp = 0; jp < 4; jp++)
            unpack2(acc[i][jp], vals[jp*2], vals[jp*2 + 1]);
        #pragma unroll
        for (int j = 0; j < 8; j++) {
            int col = n0 + tx*8 + j;
            if (col >= N) continue;
            float v = vals[j];
            long o = (long)row*N + col;
            if (MODE == 0) {
                C[o] = tanhf(v + aux1[row]*a2[col] + bptr[col]);
            } else if (MODE == 1) {
                C[o] = tanhf(v + bptr[col]);
            } else if (MODE == 2) {
                C[o] = C[o] + 0.25f*(v + bptr[col]);
            } else if (MODE == 3) {
                v += bptr[col] + a2[(row >> 10)*Hh + col];
                float last = aux1[(long)row*Hh + (Hh-1)];
                C[o] = (last == 0.f) ? 0.f : v;
            } else {
                C[o] = v + bptr[col];
            }
        }
    }
}

// ---------------------------------------------------------------------------
// Attention: one CTA per (b, 32-row q-tile).
// smem: Sc[32][1024] + Qs[32][256] + Ks[256][64] (swizzled transpose) = 229376 B
// ---------------------------------------------------------------------------
__global__ __launch_bounds__(256)
void attn_kernel(const float* __restrict__ qkv, float* __restrict__ ctx)
{
    extern __shared__ float sm[];
    float* Sc = sm;                    // 32*1024
    float* Qs = Sc + 32*1024;          // 32*256
    float* Ks = Qs + 32*256;           // 256*64, Ks[d*64 + (key ^ 4*(d&15))]

    int b  = blockIdx.y;
    int q0 = blockIdx.x * 32;
    const float* Qg = qkv              + (long)b*Ss*Hh + (long)q0*Hh;
    const float* Kg = qkv + 1L*Mtot*Hh + (long)b*Ss*Hh;
    const float* Vg = qkv + 2L*Mtot*Hh + (long)b*Ss*Hh;

    int tid = threadIdx.x;
    for (int i = tid; i < 32*256; i += 256) Qs[i] = Qg[i];

    int tx = tid & 15, ty = tid >> 4;
    int r0 = ty*2, r1 = r0 + 1;
    const float scale = 0.0625f;       // 1/sqrt(256)
    int swd = 4*(tid & 15);            // store-side swizzle (d = tid)

    // ---- Phase 1: scores ----
    for (int kt = 0; kt < 16; kt++) {
        __syncthreads();   // Ks free to overwrite (also covers Qs on kt=0)
        #pragma unroll 8
        for (int it = 0; it < 64; it++)
            Ks[tid*64 + (it ^ swd)] = Kg[(long)(kt*64 + it)*Hh + tid];
        __syncthreads();

        u64 a00 = 0, a01 = 0, a10 = 0, a11 = 0;
        #pragma unroll 4
        for (int d = 0; d < 256; d += 4) {
            float4 qa = *(const float4*)&Qs[r0*256 + d];
            float4 qb = *(const float4*)&Qs[r1*256 + d];
            float qav[4] = {qa.x, qa.y, qa.z, qa.w};
            float qbv[4] = {qb.x, qb.y, qb.z, qb.w};
            int c4 = 4*(d & 15);
            #pragma unroll
            for (int dd = 0; dd < 4; dd++) {
                ulonglong2 kp = *(const ulonglong2*)
                    &Ks[(d + dd)*64 + ((tx*4) ^ (c4 + 4*dd))];
                u64 qpa = pack2(qav[dd], qav[dd]);
                u64 qpb = pack2(qbv[dd], qbv[dd]);
                ffma2(a00, qpa, kp.x); ffma2(a01, qpa, kp.y);
                ffma2(a10, qpb, kp.x); ffma2(a11, qpb, kp.y);
            }
        }
        float x0, x1, x2, x3;
        unpack2(a00, x0, x1); unpack2(a01, x2, x3);
        Sc[r0*1024 + kt*64 + tx*4 + 0] = x0*scale;
        Sc[r0*1024 + kt*64 + tx*4 + 1] = x1*scale;
        Sc[r0*1024 + kt*64 + tx*4 + 2] = x2*scale;
        Sc[r0*1024 + kt*64 + tx*4 + 3] = x3*scale;
        unpack2(a10, x0, x1); unpack2(a11, x2, x3);
        Sc[r1*1024 + kt*64 + tx*4 + 0] = x0*scale;
        Sc[r1*1024 + kt*64 + tx*4 + 1] = x1*scale;
        Sc[r1*1024 + kt*64 + tx*4 + 2] = x2*scale;
        Sc[r1*1024 + kt*64 + tx*4 + 3] = x3*scale;
    }
    __syncthreads();

    // ---- Phase 2: softmax, one warp per 4 rows ----
    int lane = tid & 31, w = tid >> 5;
    for (int rr = 0; rr < 4; rr++) {
        int r = w*4 + rr;
        float* row = Sc + r*1024;
        float mx = -1e30f;
        for (int j = lane; j < 1024; j += 32) mx = fmaxf(mx, row[j]);
        #pragma unroll
        for (int o = 16; o; o >>= 1) mx = fmaxf(mx, __shfl_xor_sync(0xffffffffu, mx, o));
        float s = 0.f;
        for (int j = lane; j < 1024; j += 32) {
            float e = __expf(row[j] - mx);
            row[j] = e;
            s += e;
        }
        #pragma unroll
        for (int o = 16; o; o >>= 1) s += __shfl_xor_sync(0xffffffffu, s, o);
        float inv = 1.f / s;
        for (int j = lane; j < 1024; j += 32) row[j] *= inv;
    }
    __syncthreads();

    // ---- Phase 3: ctx = P @ V with f32x2 (pairs along k) ----
    u64 accp[32];
    #pragma unroll
    for (int r = 0; r < 32; r++) accp[r] = 0ull;

    float vcur[8];
    #pragma unroll
    for (int t = 0; t < 8; t++) vcur[t] = Vg[(long)t*Hh + tid];

    for (int j = 0; j < 1024; j += 8) {
        float vnxt[8];
        if (j + 8 < 1024) {
            #pragma unroll
            for (int t = 0; t < 8; t++) vnxt[t] = Vg[(long)(j + 8 + t)*Hh + tid];
        } else {
            #pragma unroll
            for (int t = 0; t < 8; t++) vnxt[t] = 0.f;
        }
        #pragma unroll
        for (int p = 0; p < 4; p++) {
            u64 vp = pack2(vcur[2*p], vcur[2*p + 1]);
            #pragma unroll
            for (int r = 0; r < 32; r++)
                ffma2(accp[r], *(const u64*)&Sc[r*1024 + j + 2*p], vp);
        }
        #pragma unroll
        for (int t = 0; t < 8; t++) vcur[t] = vnxt[t];
    }

    #pragma unroll
    for (int r = 0; r < 32; r++) {
        float lo, hi;
        unpack2(accp[r], lo, hi);
        ctx[(long)b*Ss*Hh + (long)(q0 + r)*Hh + tid] = lo + hi;
    }
}

// ---------------------------------------------------------------------------
extern "C" void kernel_launch(void* const* d_in, const int* in_sizes, int n_in,
                              void* d_out, int out_size)
{
    const float* eco_data = (const float*)d_in[0];
    const float* tran     = (const float*)d_in[1];
    const float* time_x   = (const float*)d_in[3];
    const float* W_eco = (const float*)d_in[6];
    const float* b_eco = (const float*)d_in[7];
    const float* W_in  = (const float*)d_in[8];
    const float* W_t   = (const float*)d_in[9];
    const float* b_in  = (const float*)d_in[10];
    const float* W_f1  = (const float*)d_in[11];
    const float* b_f1  = (const float*)d_in[12];
    const float* W_f2  = (const float*)d_in[13];
    const float* b_f2  = (const float*)d_in[14];
    const float* W_out = (const float*)d_in[15];
    const float* b_out = (const float*)d_in[16];
    const float* W_lin = (const float*)d_in[17];
    const float* b_lin = (const float*)d_in[18];
    float* out = (float*)d_out;

    float *h, *hid, *qkv, *ctx, *eco;
    cudaGetSymbolAddress((void**)&h,   g_h);
    cudaGetSymbolAddress((void**)&hid, g_hid);
    cudaGetSymbolAddress((void**)&qkv, g_qkv);
    cudaGetSymbolAddress((void**)&ctx, g_ctx);
    cudaGetSymbolAddress((void**)&eco, g_eco);

    dim3 blk(256);

    eco_kernel<<<Bb, Hh>>>(eco_data, W_eco, b_eco, eco);

    // h = tanh(tran @ W_in + time_x * W_t + b_in)   [3][M][L]
    gemm_kernel<0><<<dim3(Mtot/64, (Ll+63)/64, 3), blk>>>(
        tran, W_in, h, Mtot, Ll, Hh,
        0L, (long)Hh*Ll, (long)Mtot*Ll, Ll, b_in, time_x, W_t, Ll);

    // 4 Euler steps
    for (int it = 0; it < 4; it++) {
        gemm_kernel<1><<<dim3(Mtot/64, (Oo+63)/64, 3), blk>>>(
            h, W_f1, hid, Mtot, Oo, Ll,
            (long)Mtot*Ll, (long)Ll*Oo, (long)Mtot*Oo, Oo, b_f1, nullptr, nullptr, 0);
        gemm_kernel<2><<<dim3(Mtot/64, (Ll+63)/64, 3), blk>>>(
            hid, W_f2, h, Mtot, Ll, Oo,
            (long)Mtot*Oo, (long)Oo*Ll, (long)Mtot*Ll, Ll, b_f2, nullptr, nullptr, 0);
    }

    // qkv = mask * (h @ W_out + b_out + eco)    [3][M][H]
    gemm_kernel<3><<<dim3(Mtot/64, Hh/64, 3), blk>>>(
        h, W_out, qkv, Mtot, Hh, Ll,
        (long)Mtot*Ll, (long)Ll*Hh, (long)Mtot*Hh, Hh, b_out, tran, eco, 0);

    // attention
    size_t smem = (size_t)(32*1024 + 32*256 + 256*64) * sizeof(float); // 229376
    cudaFuncSetAttribute(attn_kernel, cudaFuncAttributeMaxDynamicSharedMemorySize, (int)smem);
    attn_kernel<<<dim3(Ss/32, Bb), blk, smem>>>(qkv, ctx);

    // out = ctx @ W_lin + b_lin   [M][P]
    gemm_kernel<4><<<dim3(Mtot/64, (Pp+63)/64, 1), blk>>>(
        ctx, W_lin, out, Mtot, Pp, Hh,
        0L, 0L, 0L, 0, b_lin, nullptr, nullptr, 0);
}

// round 9
// speedup vs baseline: 1.4019x; 1.4019x over previous
#include <cuda_runtime.h>
#include <cuda_bf16.h>
#include <mma.h>
#include <math.h>

using namespace nvcuda;

// Problem constants
#define Bb   32
#define Ss   1024
#define Hh   256
#define Pp   96
#define Ll   200
#define Oo   200
#define Ee   64
#define Mtot (Bb*Ss)   // 32768

typedef __nv_bfloat16 bf16;

// ---------------------------------------------------------------------------
// Scratch
// ---------------------------------------------------------------------------
__device__ bf16  g_thi [(long)Mtot*256];      // tran split (K=256)
__device__ bf16  g_tlo [(long)Mtot*256];
__device__ bf16  g_hhi [3L*Mtot*256];         // h split (cols 200..255 zero)
__device__ bf16  g_hlo [3L*Mtot*256];
__device__ float g_hf  [3L*Mtot*256];         // h fp32 master
__device__ bf16  g_dhi [3L*Mtot*256];         // hid split
__device__ bf16  g_dlo [3L*Mtot*256];
__device__ float g_qkv [3L*Mtot*256];
__device__ float g_ctx [(long)Mtot*256];
__device__ float g_eco [Bb*Hh];
// weight splits, B-format [3][256 n][256 k] (transposed, zero padded)
__device__ bf16 g_winh[3*256*256], g_winl[3*256*256];
__device__ bf16 g_wf1h[3*256*256], g_wf1l[3*256*256];
__device__ bf16 g_wf2h[3*256*256], g_wf2l[3*256*256];
__device__ bf16 g_woh [3*256*256], g_wol [3*256*256];

// ---------------------------------------------------------------------------
__global__ void eco_kernel(const float* __restrict__ eco_data,
                           const float* __restrict__ W_eco,
                           const float* __restrict__ b_eco,
                           float* __restrict__ out)
{
    int b = blockIdx.x;
    int h = threadIdx.x;
    float acc = b_eco[h];
    #pragma unroll 8
    for (int e = 0; e < Ee; e++)
        acc = fmaf(eco_data[b*Ee + e], W_eco[e*Hh + h], acc);
    out[b*Hh + h] = acc;
}

// split tran_data [M][256] -> bf16 hi/lo
__global__ void splitin_kernel(const float* __restrict__ X,
                               bf16* __restrict__ hi, bf16* __restrict__ lo)
{
    long i = (long)blockIdx.x*256 + threadIdx.x;
    float v = X[i];
    bf16 h = __float2bfloat16(v);
    hi[i] = h;
    lo[i] = __float2bfloat16(v - __bfloat162float(h));
}

// split+transpose weights: W[kb][k][n] -> B[kb][n][k], zero-padded [3][256][256]
__global__ void splitw_kernel(const float* __restrict__ W, int K, int N,
                              bf16* __restrict__ outHi, bf16* __restrict__ outLo)
{
    int kb = blockIdx.z;
    int idx = blockIdx.x*256 + threadIdx.x;   // 0..65535
    int n = idx >> 8, k = idx & 255;
    float v = (k < K && n < N) ? W[((long)kb*K + k)*N + n] : 0.f;
    bf16 h = __float2bfloat16(v);
    long o = ((long)kb*256 + n)*256 + k;
    outHi[o] = h;
    outLo[o] = __float2bfloat16(v - __bfloat162float(h));
}

// ---------------------------------------------------------------------------
// WMMA split-bf16 GEMM: C[128 m][128 n] per CTA = A[M,256] @ B^T (B: [n][k]).
// grid (M/128, 2, 3). 8 warps: wm = wid&3 (32 rows), wn = wid>>2 (64 cols).
// 3-term: Ahi*Bhi + Ahi*Blo + Alo*Bhi, fp32 accum.
// MODE 0: h-init   r = tanh(acc + timex[row]*Wt[col] + bias[col]); write hi/lo/f
// MODE 1: hid      r = tanh(acc + bias[col]);                      write hi/lo
// MODE 2: update   r = hf + 0.25*(acc + bias[col]);                write hi/lo/f
// MODE 3: qkv      r = mask * (acc + bias[col] + eco);             write f only
// ---------------------------------------------------------------------------
template<int MODE>
__global__ __launch_bounds__(256, 2)
void wgemm(const bf16* __restrict__ Ahi, const bf16* __restrict__ Alo,
           long aKbStride, int Ksteps,
           const bf16* __restrict__ Bhi, const bf16* __restrict__ Blo,
           int Nvalid,
           const float* __restrict__ bias,
           const float* __restrict__ timex, const float* __restrict__ Wt,
           const float* __restrict__ tran, const float* __restrict__ eco,
           bf16* __restrict__ OutHi, bf16* __restrict__ OutLo,
           float* __restrict__ OutF)
{
    __shared__ bf16 sAh[128][24], sAl[128][24], sBh[128][24], sBl[128][24];
    __shared__ float wbuf[8][16][20];

    int tid = threadIdx.x;
    int wid = tid >> 5, lane = tid & 31;
    int wm = wid & 3, wn = wid >> 2;
    int kb = blockIdx.z;
    long m0 = (long)blockIdx.x * 128;
    int n0 = blockIdx.y * 128;

    const bf16* Ah = Ahi + (long)kb * aKbStride;
    const bf16* Al = Alo + (long)kb * aKbStride;
    const bf16* Bh = Bhi + (long)kb * 65536 + (long)n0 * 256;
    const bf16* Bl = Blo + (long)kb * 65536 + (long)n0 * 256;
    bf16*  oHi = OutHi ? OutHi + (long)kb * Mtot * 256 : (bf16*)0;
    bf16*  oLo = OutLo ? OutLo + (long)kb * Mtot * 256 : (bf16*)0;
    float* oF  = OutF  ? OutF  + (long)kb * Mtot * 256 : (float*)0;

    wmma::fragment<wmma::accumulator, 16, 16, 16, float> acc[2][4];
    #pragma unroll
    for (int im = 0; im < 2; im++)
        #pragma unroll
        for (int in = 0; in < 4; in++) wmma::fill_fragment(acc[im][in], 0.f);

    int lr = tid >> 1;              // 0..127
    int lh = (tid & 1) * 8;         // 0 or 8

    for (int k = 0; k < Ksteps; k++) {
        int k0 = k * 16;
        __syncthreads();
        *(uint4*)&sAh[lr][lh] = *(const uint4*)&Ah[(m0 + lr)*256 + k0 + lh];
        *(uint4*)&sAl[lr][lh] = *(const uint4*)&Al[(m0 + lr)*256 + k0 + lh];
        *(uint4*)&sBh[lr][lh] = *(const uint4*)&Bh[(long)lr*256 + k0 + lh];
        *(uint4*)&sBl[lr][lh] = *(const uint4*)&Bl[(long)lr*256 + k0 + lh];
        __syncthreads();

        wmma::fragment<wmma::matrix_a, 16, 16, 16, bf16, wmma::row_major> afh[2], afl[2];
        #pragma unroll
        for (int im = 0; im < 2; im++) {
            wmma::load_matrix_sync(afh[im], &sAh[wm*32 + im*16][0], 24);
            wmma::load_matrix_sync(afl[im], &sAl[wm*32 + im*16][0], 24);
        }
        #pragma unroll
        for (int in = 0; in < 4; in++) {
            wmma::fragment<wmma::matrix_b, 16, 16, 16, bf16, wmma::col_major> bfh, bfl;
            wmma::load_matrix_sync(bfh, &sBh[wn*64 + in*16][0], 24);
            wmma::load_matrix_sync(bfl, &sBl[wn*64 + in*16][0], 24);
            #pragma unroll
            for (int im = 0; im < 2; im++) {
                wmma::mma_sync(acc[im][in], afh[im], bfh, acc[im][in]);
                wmma::mma_sync(acc[im][in], afh[im], bfl, acc[im][in]);
                wmma::mma_sync(acc[im][in], afl[im], bfh, acc[im][in]);
            }
        }
    }

    // Fused epilogue, one fragment at a time via per-warp smem staging
    float* wb = &wbuf[wid][0][0];
    #pragma unroll
    for (int im = 0; im < 2; im++) {
        #pragma unroll
        for (int in = 0; in < 4; in++) {
            wmma::store_matrix_sync(wb, acc[im][in], 20, wmma::mem_row_major);
            __syncwarp();
            #pragma unroll
            for (int e = 0; e < 8; e++) {
                int idx = lane*8 + e;
                int rr = idx >> 4, cc = idx & 15;
                float a = wb[rr*20 + cc];
                long row = m0 + wm*32 + im*16 + rr;
                int col = n0 + wn*64 + in*16 + cc;
                float r_ = 0.f;
                if (MODE == 0) {
                    if (col < Nvalid)
                        r_ = tanhf(a + timex[row]*Wt[kb*Nvalid + col]
                                   + bias[kb*Nvalid + col]);
                } else if (MODE == 1) {
                    if (col < Nvalid)
                        r_ = tanhf(a + bias[kb*Nvalid + col]);
                } else if (MODE == 2) {
                    if (col < Nvalid)
                        r_ = oF[row*256 + col] + 0.25f*(a + bias[kb*Nvalid + col]);
                } else {
                    float v = a + bias[kb*Nvalid + col]
                              + eco[(int)(row >> 10)*256 + col];
                    float last = tran[row*256 + 255];
                    r_ = (last == 0.f) ? 0.f : v;
                }
                long o = row*256 + col;
                if (MODE == 3) {
                    oF[o] = r_;
                } else {
                    bf16 hq = __float2bfloat16(r_);
                    oHi[o] = hq;
                    oLo[o] = __float2bfloat16(r_ - __bfloat162float(hq));
                    if (MODE != 1) oF[o] = r_;
                }
            }
            __syncwarp();
        }
    }
}

// ---------------------------------------------------------------------------
// Scalar head GEMM: out = ctx @ W_lin + b_lin
// ---------------------------------------------------------------------------
__global__ __launch_bounds__(256)
void head_gemm(const float* __restrict__ A, const float* __restrict__ W,
               float* __restrict__ C, int M, int N, int K,
               const float* __restrict__ bias)
{
    __shared__ float As[64][17];
    __shared__ float Ws[16][64];
    int tid = threadIdx.x;
    int tx = tid & 15, ty = tid >> 4;
    int m0 = blockIdx.x * 64, n0 = blockIdx.y * 64;
    float acc[4][4] = {};
    for (int k0 = 0; k0 < K; k0 += 16) {
        #pragma unroll
        for (int i = 0; i < 4; i++) {
            int idx = tid + i*256;
            int r = idx >> 4, c = idx & 15;
            As[r][c] = A[(long)(m0 + r)*K + k0 + c];
        }
        #pragma unroll
        for (int i = 0; i < 4; i++) {
            int idx = tid + i*256;
            int r = idx >> 6, c = idx & 63;
            int gc = n0 + c;
            Ws[r][c] = (gc < N) ? W[(long)(k0 + r)*N + gc] : 0.f;
        }
        __syncthreads();
        #pragma unroll
        for (int kk = 0; kk < 16; kk++) {
            float a[4];
            #pragma unroll
            for (int i = 0; i < 4; i++) a[i] = As[ty*4 + i][kk];
            float4 b4 = *(const float4*)&Ws[kk][tx*4];
            float bv[4] = {b4.x, b4.y, b4.z, b4.w};
            #pragma unroll
            for (int i = 0; i < 4; i++)
                #pragma unroll
                for (int j = 0; j < 4; j++)
                    acc[i][j] = fmaf(a[i], bv[j], acc[i][j]);
        }
        __syncthreads();
    }
    #pragma unroll
    for (int i = 0; i < 4; i++) {
        int row = m0 + ty*4 + i;
        #pragma unroll
        for (int j = 0; j < 4; j++) {
            int col = n0 + tx*4 + j;
            if (col < N) C[(long)row*N + col] = acc[i][j] + bias[col];
        }
    }
}

// ---------------------------------------------------------------------------
// Attention (R3, known good): one CTA per (b, 32-row q-tile).
// ---------------------------------------------------------------------------
__global__ __launch_bounds__(256)
void attn_kernel(const float* __restrict__ qkv, float* __restrict__ ctx)
{
    extern __shared__ float sm[];
    float* Sc = sm;                    // 32*1024
    float* Qs = Sc + 32*1024;          // 32*256
    float* Ks = Qs + 32*256;           // 256*65

    int b  = blockIdx.y;
    int q0 = blockIdx.x * 32;
    const float* Qg = qkv              + (long)b*Ss*Hh + (long)q0*Hh;
    const float* Kg = qkv + 1L*Mtot*Hh + (long)b*Ss*Hh;
    const float* Vg = qkv + 2L*Mtot*Hh + (long)b*Ss*Hh;

    int tid = threadIdx.x;
    for (int i = tid; i < 32*256; i += 256) Qs[i] = Qg[i];
    __syncthreads();

    int tx = tid & 15, ty = tid >> 4;
    const float scale = 0.0625f;

    for (int kt = 0; kt < 16; kt++) {
        #pragma unroll 8
        for (int it = 0; it < 64; it++)
            Ks[tid*65 + it] = Kg[(long)(kt*64 + it)*Hh + tid];
        __syncthreads();

        float acc[2][4] = {};
        int r0 = ty*2, r1 = r0 + 1;
        for (int d = 0; d < 256; d += 4) {
            float4 qa = *(const float4*)&Qs[r0*256 + d];
            float4 qb = *(const float4*)&Qs[r1*256 + d];
            float qav[4] = {qa.x, qa.y, qa.z, qa.w};
            float qbv[4] = {qb.x, qb.y, qb.z, qb.w};
            #pragma unroll
            for (int dd = 0; dd < 4; dd++) {
                #pragma unroll
                for (int j = 0; j < 4; j++) {
                    float kv = Ks[(d + dd)*65 + tx*4 + j];
                    acc[0][j] = fmaf(qav[dd], kv, acc[0][j]);
                    acc[1][j] = fmaf(qbv[dd], kv, acc[1][j]);
                }
            }
        }
        #pragma unroll
        for (int j = 0; j < 4; j++) {
            Sc[r0*1024 + kt*64 + tx*4 + j] = acc[0][j]*scale;
            Sc[r1*1024 + kt*64 + tx*4 + j] = acc[1][j]*scale;
        }
        __syncthreads();
    }

    int lane = tid & 31, w = tid >> 5;
    for (int rr = 0; rr < 4; rr++) {
        int r = w*4 + rr;
        float* row = Sc + r*1024;
        float mx = -1e30f;
        for (int j = lane; j < 1024; j += 32) mx = fmaxf(mx, row[j]);
        #pragma unroll
        for (int o = 16; o; o >>= 1) mx = fmaxf(mx, __shfl_xor_sync(0xffffffffu, mx, o));
        float s = 0.f;
        for (int j = lane; j < 1024; j += 32) {
            float e = __expf(row[j] - mx);
            row[j] = e;
            s += e;
        }
        #pragma unroll
        for (int o = 16; o; o >>= 1) s += __shfl_xor_sync(0xffffffffu, s, o);
        float inv = 1.f / s;
        for (int j = lane; j < 1024; j += 32) row[j] *= inv;
    }
    __syncthreads();

    float acc2[32];
    #pragma unroll
    for (int r = 0; r < 32; r++) acc2[r] = 0.f;
    for (int j = 0; j < 1024; j += 4) {
        float v0 = Vg[(long)(j+0)*Hh + tid];
        float v1 = Vg[(long)(j+1)*Hh + tid];
        float v2 = Vg[(long)(j+2)*Hh + tid];
        float v3 = Vg[(long)(j+3)*Hh + tid];
        #pragma unroll
        for (int r = 0; r < 32; r++) {
            float4 p = *(const float4*)&Sc[r*1024 + j];
            acc2[r] = fmaf(p.x, v0, fmaf(p.y, v1, fmaf(p.z, v2, fmaf(p.w, v3, acc2[r]))));
        }
    }
    #pragma unroll
    for (int r = 0; r < 32; r++)
        ctx[(long)b*Ss*Hh + (long)(q0 + r)*Hh + tid] = acc2[r];
}

// ---------------------------------------------------------------------------
extern "C" void kernel_launch(void* const* d_in, const int* in_sizes, int n_in,
                              void* d_out, int out_size)
{
    const float* eco_data = (const float*)d_in[0];
    const float* tran     = (const float*)d_in[1];
    const float* time_x   = (const float*)d_in[3];
    const float* W_eco = (const float*)d_in[6];
    const float* b_eco = (const float*)d_in[7];
    const float* W_in  = (const float*)d_in[8];
    const float* W_t   = (const float*)d_in[9];
    const float* b_in  = (const float*)d_in[10];
    const float* W_f1  = (const float*)d_in[11];
    const float* b_f1  = (const float*)d_in[12];
    const float* W_f2  = (const float*)d_in[13];
    const float* b_f2  = (const float*)d_in[14];
    const float* W_out = (const float*)d_in[15];
    const float* b_out = (const float*)d_in[16];
    const float* W_lin = (const float*)d_in[17];
    const float* b_lin = (const float*)d_in[18];
    float* out = (float*)d_out;

    bf16 *thi, *tlo, *hhi, *hlo, *dhi, *dlo;
    bf16 *winh, *winl, *wf1h, *wf1l, *wf2h, *wf2l, *woh, *wol;
    float *hf, *qkv, *ctx, *eco;
    cudaGetSymbolAddress((void**)&thi, g_thi);  cudaGetSymbolAddress((void**)&tlo, g_tlo);
    cudaGetSymbolAddress((void**)&hhi, g_hhi);  cudaGetSymbolAddress((void**)&hlo, g_hlo);
    cudaGetSymbolAddress((void**)&dhi, g_dhi);  cudaGetSymbolAddress((void**)&dlo, g_dlo);
    cudaGetSymbolAddress((void**)&hf,  g_hf);
    cudaGetSymbolAddress((void**)&winh, g_winh); cudaGetSymbolAddress((void**)&winl, g_winl);
    cudaGetSymbolAddress((void**)&wf1h, g_wf1h); cudaGetSymbolAddress((void**)&wf1l, g_wf1l);
    cudaGetSymbolAddress((void**)&wf2h, g_wf2h); cudaGetSymbolAddress((void**)&wf2l, g_wf2l);
    cudaGetSymbolAddress((void**)&woh, g_woh);   cudaGetSymbolAddress((void**)&wol, g_wol);
    cudaGetSymbolAddress((void**)&qkv, g_qkv);
    cudaGetSymbolAddress((void**)&ctx, g_ctx);
    cudaGetSymbolAddress((void**)&eco, g_eco);

    eco_kernel<<<Bb, Hh>>>(eco_data, W_eco, b_eco, eco);
    splitin_kernel<<<Mtot, 256>>>(tran, thi, tlo);
    splitw_kernel<<<dim3(256,1,3), 256>>>(W_in,  256, 200, winh, winl);
    splitw_kernel<<<dim3(256,1,3), 256>>>(W_f1,  200, 200, wf1h, wf1l);
    splitw_kernel<<<dim3(256,1,3), 256>>>(W_f2,  200, 200, wf2h, wf2l);
    splitw_kernel<<<dim3(256,1,3), 256>>>(W_out, 200, 256, woh,  wol);

    dim3 wg(Mtot/128, 2, 3);

    // h = tanh(tran @ W_in + time_x*W_t + b_in)   K=256 (16 steps)
    wgemm<0><<<wg, 256>>>(thi, tlo, 0L, 16, winh, winl, 200,
        b_in, time_x, W_t, nullptr, nullptr, hhi, hlo, hf);

    // 4 Euler steps, K=208 (13 steps)
    for (int it = 0; it < 4; it++) {
        wgemm<1><<<wg, 256>>>(hhi, hlo, (long)Mtot*256, 13, wf1h, wf1l, 200,
            b_f1, nullptr, nullptr, nullptr, nullptr, dhi, dlo, nullptr);
        wgemm<2><<<wg, 256>>>(dhi, dlo, (long)Mtot*256, 13, wf2h, wf2l, 200,
            b_f2, nullptr, nullptr, nullptr, nullptr, hhi, hlo, hf);
    }

    // qkv = mask * (h @ W_out + b_out + eco), K=208, N=256
    wgemm<3><<<wg, 256>>>(hhi, hlo, (long)Mtot*256, 13, woh, wol, 256,
        b_out, nullptr, nullptr, tran, eco, nullptr, nullptr, qkv);

    // attention (scalar, known good)
    size_t asmem = (size_t)(32*1024 + 32*256 + 256*65) * sizeof(float);
    cudaFuncSetAttribute(attn_kernel, cudaFuncAttributeMaxDynamicSharedMemorySize, (int)asmem);
    attn_kernel<<<dim3(Ss/32, Bb), 256, asmem>>>(qkv, ctx);

    // head
    head_gemm<<<dim3(Mtot/64, 2, 1), 256>>>(ctx, W_lin, out, Mtot, Pp, Hh, b_lin);
}

// round 10
// speedup vs baseline: 1.6547x; 1.1803x over previous
#include <cuda_runtime.h>
#include <math.h>

// Problem constants
#define Bb   32
#define Ss   1024
#define Hh   256
#define Pp   96
#define Ll   200
#define Oo   200
#define Ee   64
#define Mtot (Bb*Ss)   // 32768

// Scratch
__device__ float g_h  [3u*Mtot*Ll];
__device__ float g_hid[3u*Mtot*Ll];
__device__ float g_qkv[3u*Mtot*Hh];
__device__ float g_ctx[(unsigned)Mtot*Hh];
__device__ float g_eco[Bb*Hh];

// ---------------------------------------------------------------------------
__global__ void eco_kernel(const float* __restrict__ eco_data,
                           const float* __restrict__ W_eco,
                           const float* __restrict__ b_eco,
                           float* __restrict__ out)
{
    int b = blockIdx.x;
    int h = threadIdx.x;
    float acc = b_eco[h];
    #pragma unroll 8
    for (int e = 0; e < Ee; e++)
        acc = fmaf(eco_data[b*Ee + e], W_eco[e*Hh + h], acc);
    out[b*Hh + h] = acc;
}

// ---------------------------------------------------------------------------
// Scalar fp32 GEMM, 128x128 CTA tile, 8x8 per thread, double-buffered.
// C[M,N] = A[M,K] @ W[K,N], per-kb batch via blockIdx.z strides.
// MODE 0: h-init   C = tanh(acc + timef[row]*Wt[col] + bias[col])
// MODE 1: hid      C = tanh(acc + bias[col])
// MODE 2: update   C += 0.25*(acc + bias[col])
// MODE 3: qkv      C = mask(row) * (acc + bias[col] + eco[b(row)][col])
// MODE 4: head     C = acc + bias[col]
// ---------------------------------------------------------------------------
template<int MODE>
__global__ __launch_bounds__(256, 2)
void gemm_kernel(const float* __restrict__ A, const float* __restrict__ W,
                 float* __restrict__ C,
                 int M, int N, int K,
                 long aStride, long wStride, long cStride, int biasStride,
                 const float* __restrict__ bias,
                 const float* __restrict__ aux1,
                 const float* __restrict__ aux2, int aux2Stride)
{
    int kb = blockIdx.z;
    A += (long)kb * aStride;
    W += (long)kb * wStride;
    C += (long)kb * cStride;
    const float* bptr = bias + (long)kb * biasStride;
    const float* a2   = aux2 ? (aux2 + (long)kb * aux2Stride) : nullptr;

    __shared__ __align__(16) float As[2][16][132];   // transposed A: [k][row]
    __shared__ __align__(16) float Ws[2][16][132];   // [k][col]

    int tid = threadIdx.x;
    int tx = tid & 15, ty = tid >> 4;
    long m0 = (long)blockIdx.x * 128;
    int  n0 = blockIdx.y * 128;

    // A loader: 2 float4/thread. f4 = tid + 256*i -> row = f4>>2, kc4 = f4&3
    // W loader: 2 float4/thread. f4 = tid + 256*i -> r = f4>>5,  c4  = f4&31
    int aRow0 = tid >> 2,        aK0 = (tid & 3) * 4;
    int aRow1 = (tid + 256) >> 2, aK1 = aK0;          // same kc pattern
    int wR0 = tid >> 5,          wC0 = (tid & 31) * 4;
    int wR1 = (tid + 256) >> 5,  wC1 = wC0;

    int P = (K + 15) >> 4;

    float4 ar0, ar1, wr0, wr1;
    const float4 z4 = make_float4(0.f, 0.f, 0.f, 0.f);

    // preload panel 0
    {
        int k0 = 0;
        ar0 = (k0 + aK0 + 3 < K) ? *(const float4*)&A[(m0 + aRow0)*K + k0 + aK0] : z4;
        ar1 = (k0 + aK1 + 3 < K) ? *(const float4*)&A[(m0 + aRow1)*K + k0 + aK1] : z4;
        wr0 = (k0 + wR0 < K && n0 + wC0 + 3 < N) ? *(const float4*)&W[(long)(k0 + wR0)*N + n0 + wC0] : z4;
        wr1 = (k0 + wR1 < K && n0 + wC1 + 3 < N) ? *(const float4*)&W[(long)(k0 + wR1)*N + n0 + wC1] : z4;
        As[0][aK0 + 0][aRow0] = ar0.x; As[0][aK0 + 1][aRow0] = ar0.y;
        As[0][aK0 + 2][aRow0] = ar0.z; As[0][aK0 + 3][aRow0] = ar0.w;
        As[0][aK1 + 0][aRow1] = ar1.x; As[0][aK1 + 1][aRow1] = ar1.y;
        As[0][aK1 + 2][aRow1] = ar1.z; As[0][aK1 + 3][aRow1] = ar1.w;
        *(float4*)&Ws[0][wR0][wC0] = wr0;
        *(float4*)&Ws[0][wR1][wC1] = wr1;
    }
    __syncthreads();

    float acc[8][8];
    #pragma unroll
    for (int i = 0; i < 8; i++)
        #pragma unroll
        for (int j = 0; j < 8; j++) acc[i][j] = 0.f;

    for (int p = 0; p < P; p++) {
        int cur = p & 1, nxt = cur ^ 1;
        if (p + 1 < P) {
            int k0 = (p + 1) << 4;
            ar0 = (k0 + aK0 + 3 < K) ? *(const float4*)&A[(m0 + aRow0)*K + k0 + aK0] : z4;
            ar1 = (k0 + aK1 + 3 < K) ? *(const float4*)&A[(m0 + aRow1)*K + k0 + aK1] : z4;
            wr0 = (k0 + wR0 < K && n0 + wC0 + 3 < N) ? *(const float4*)&W[(long)(k0 + wR0)*N + n0 + wC0] : z4;
            wr1 = (k0 + wR1 < K && n0 + wC1 + 3 < N) ? *(const float4*)&W[(long)(k0 + wR1)*N + n0 + wC1] : z4;
        }
        #pragma unroll
        for (int kk = 0; kk < 16; kk++) {
            float4 a0 = *(const float4*)&As[cur][kk][ty*8];
            float4 a1 = *(const float4*)&As[cur][kk][ty*8 + 4];
            float4 b0 = *(const float4*)&Ws[cur][kk][tx*8];
            float4 b1 = *(const float4*)&Ws[cur][kk][tx*8 + 4];
            float av[8] = {a0.x, a0.y, a0.z, a0.w, a1.x, a1.y, a1.z, a1.w};
            float bv[8] = {b0.x, b0.y, b0.z, b0.w, b1.x, b1.y, b1.z, b1.w};
            #pragma unroll
            for (int i = 0; i < 8; i++)
                #pragma unroll
                for (int j = 0; j < 8; j++)
                    acc[i][j] = fmaf(av[i], bv[j], acc[i][j]);
        }
        if (p + 1 < P) {
            As[nxt][aK0 + 0][aRow0] = ar0.x; As[nxt][aK0 + 1][aRow0] = ar0.y;
            As[nxt][aK0 + 2][aRow0] = ar0.z; As[nxt][aK0 + 3][aRow0] = ar0.w;
            As[nxt][aK1 + 0][aRow1] = ar1.x; As[nxt][aK1 + 1][aRow1] = ar1.y;
            As[nxt][aK1 + 2][aRow1] = ar1.z; As[nxt][aK1 + 3][aRow1] = ar1.w;
            *(float4*)&Ws[nxt][wR0][wC0] = wr0;
            *(float4*)&Ws[nxt][wR1][wC1] = wr1;
        }
        __syncthreads();
    }

    // epilogue
    #pragma unroll
    for (int i = 0; i < 8; i++) {
        long row = m0 + ty*8 + i;
        float tf   = (MODE == 0) ? aux1[row] : 0.f;
        float last = (MODE == 3) ? aux1[row*Hh + (Hh-1)] : 0.f;
        #pragma unroll
        for (int j = 0; j < 8; j++) {
            int col = n0 + tx*8 + j;
            if (col >= N) continue;
            float v = acc[i][j];
            long o = row*N + col;
            if (MODE == 0) {
                C[o] = tanhf(v + tf*a2[col] + bptr[col]);
            } else if (MODE == 1) {
                C[o] = tanhf(v + bptr[col]);
            } else if (MODE == 2) {
                C[o] = C[o] + 0.25f*(v + bptr[col]);
            } else if (MODE == 3) {
                v += bptr[col] + a2[(int)(row >> 10)*Hh + col];
                C[o] = (last == 0.f) ? 0.f : v;
            } else {
                C[o] = v + bptr[col];
            }
        }
    }
}

// ---------------------------------------------------------------------------
// Attention (R3, known good): one CTA per (b, 32-row q-tile).
// smem: Sc[32][1024] + Qs[32][256] + Ks[256][65] = 230400 B
// ---------------------------------------------------------------------------
__global__ __launch_bounds__(256)
void attn_kernel(const float* __restrict__ qkv, float* __restrict__ ctx)
{
    extern __shared__ float sm[];
    float* Sc = sm;                    // 32*1024
    float* Qs = Sc + 32*1024;          // 32*256
    float* Ks = Qs + 32*256;           // 256*65

    int b  = blockIdx.y;
    int q0 = blockIdx.x * 32;
    const float* Qg = qkv              + (long)b*Ss*Hh + (long)q0*Hh;
    const float* Kg = qkv + 1L*Mtot*Hh + (long)b*Ss*Hh;
    const float* Vg = qkv + 2L*Mtot*Hh + (long)b*Ss*Hh;

    int tid = threadIdx.x;
    for (int i = tid; i < 32*256; i += 256) Qs[i] = Qg[i];
    __syncthreads();

    int tx = tid & 15, ty = tid >> 4;
    const float scale = 0.0625f;

    for (int kt = 0; kt < 16; kt++) {
        #pragma unroll 8
        for (int it = 0; it < 64; it++)
            Ks[tid*65 + it] = Kg[(long)(kt*64 + it)*Hh + tid];
        __syncthreads();

        float acc[2][4] = {};
        int r0 = ty*2, r1 = r0 + 1;
        for (int d = 0; d < 256; d += 4) {
            float4 qa = *(const float4*)&Qs[r0*256 + d];
            float4 qb = *(const float4*)&Qs[r1*256 + d];
            float qav[4] = {qa.x, qa.y, qa.z, qa.w};
            float qbv[4] = {qb.x, qb.y, qb.z, qb.w};
            #pragma unroll
            for (int dd = 0; dd < 4; dd++) {
                #pragma unroll
                for (int j = 0; j < 4; j++) {
                    float kv = Ks[(d + dd)*65 + tx*4 + j];
                    acc[0][j] = fmaf(qav[dd], kv, acc[0][j]);
                    acc[1][j] = fmaf(qbv[dd], kv, acc[1][j]);
                }
            }
        }
        #pragma unroll
        for (int j = 0; j < 4; j++) {
            Sc[r0*1024 + kt*64 + tx*4 + j] = acc[0][j]*scale;
            Sc[r1*1024 + kt*64 + tx*4 + j] = acc[1][j]*scale;
        }
        __syncthreads();
    }

    int lane = tid & 31, w = tid >> 5;
    for (int rr = 0; rr < 4; rr++) {
        int r = w*4 + rr;
        float* row = Sc + r*1024;
        float mx = -1e30f;
        for (int j = lane; j < 1024; j += 32) mx = fmaxf(mx, row[j]);
        #pragma unroll
        for (int o = 16; o; o >>= 1) mx = fmaxf(mx, __shfl_xor_sync(0xffffffffu, mx, o));
        float s = 0.f;
        for (int j = lane; j < 1024; j += 32) {
            float e = __expf(row[j] - mx);
            row[j] = e;
            s += e;
        }
        #pragma unroll
        for (int o = 16; o; o >>= 1) s += __shfl_xor_sync(0xffffffffu, s, o);
        float inv = 1.f / s;
        for (int j = lane; j < 1024; j += 32) row[j] *= inv;
    }
    __syncthreads();

    float acc2[32];
    #pragma unroll
    for (int r = 0; r < 32; r++) acc2[r] = 0.f;
    for (int j = 0; j < 1024; j += 4) {
        float v0 = Vg[(long)(j+0)*Hh + tid];
        float v1 = Vg[(long)(j+1)*Hh + tid];
        float v2 = Vg[(long)(j+2)*Hh + tid];
        float v3 = Vg[(long)(j+3)*Hh + tid];
        #pragma unroll
        for (int r = 0; r < 32; r++) {
            float4 p = *(const float4*)&Sc[r*1024 + j];
            acc2[r] = fmaf(p.x, v0, fmaf(p.y, v1, fmaf(p.z, v2, fmaf(p.w, v3, acc2[r]))));
        }
    }
    #pragma unroll
    for (int r = 0; r < 32; r++)
        ctx[(long)b*Ss*Hh + (long)(q0 + r)*Hh + tid] = acc2[r];
}

// ---------------------------------------------------------------------------
extern "C" void kernel_launch(void* const* d_in, const int* in_sizes, int n_in,
                              void* d_out, int out_size)
{
    const float* eco_data = (const float*)d_in[0];
    const float* tran     = (const float*)d_in[1];
    const float* time_x   = (const float*)d_in[3];
    const float* W_eco = (const float*)d_in[6];
    const float* b_eco = (const float*)d_in[7];
    const float* W_in  = (const float*)d_in[8];
    const float* W_t   = (const float*)d_in[9];
    const float* b_in  = (const float*)d_in[10];
    const float* W_f1  = (const float*)d_in[11];
    const float* b_f1  = (const float*)d_in[12];
    const float* W_f2  = (const float*)d_in[13];
    const float* b_f2  = (const float*)d_in[14];
    const float* W_out = (const float*)d_in[15];
    const float* b_out = (const float*)d_in[16];
    const float* W_lin = (const float*)d_in[17];
    const float* b_lin = (const float*)d_in[18];
    float* out = (float*)d_out;

    float *h, *hid, *qkv, *ctx, *eco;
    cudaGetSymbolAddress((void**)&h,   g_h);
    cudaGetSymbolAddress((void**)&hid, g_hid);
    cudaGetSymbolAddress((void**)&qkv, g_qkv);
    cudaGetSymbolAddress((void**)&ctx, g_ctx);
    cudaGetSymbolAddress((void**)&eco, g_eco);

    dim3 blk(256);

    eco_kernel<<<Bb, Hh>>>(eco_data, W_eco, b_eco, eco);

    // h = tanh(tran @ W_in + time_x * W_t + b_in)   [3][M][L]
    gemm_kernel<0><<<dim3(Mtot/128, 2, 3), blk>>>(
        tran, W_in, h, Mtot, Ll, Hh,
        0L, (long)Hh*Ll, (long)Mtot*Ll, Ll, b_in, time_x, W_t, Ll);

    // 4 Euler steps
    for (int it = 0; it < 4; it++) {
        gemm_kernel<1><<<dim3(Mtot/128, 2, 3), blk>>>(
            h, W_f1, hid, Mtot, Oo, Ll,
            (long)Mtot*Ll, (long)Ll*Oo, (long)Mtot*Oo, Oo, b_f1, nullptr, nullptr, 0);
        gemm_kernel<2><<<dim3(Mtot/128, 2, 3), blk>>>(
            hid, W_f2, h, Mtot, Ll, Oo,
            (long)Mtot*Oo, (long)Oo*Ll, (long)Mtot*Ll, Ll, b_f2, nullptr, nullptr, 0);
    }

    // qkv = mask * (h @ W_out + b_out + eco)    [3][M][H]
    gemm_kernel<3><<<dim3(Mtot/128, 2, 3), blk>>>(
        h, W_out, qkv, Mtot, Hh, Ll,
        (long)Mtot*Ll, (long)Ll*Hh, (long)Mtot*Hh, Hh, b_out, tran, eco, 0);

    // attention
    size_t smem = (size_t)(32*1024 + 32*256 + 256*65) * sizeof(float);
    cudaFuncSetAttribute(attn_kernel, cudaFuncAttributeMaxDynamicSharedMemorySize, (int)smem);
    attn_kernel<<<dim3(Ss/32, Bb), blk, smem>>>(qkv, ctx);

    // out = ctx @ W_lin + b_lin   [M][P]
    gemm_kernel<4><<<dim3(Mtot/128, 1, 1), blk>>>(
        ctx, W_lin, out, Mtot, Pp, Hh,
        0L, 0L, 0L, 0, b_lin, nullptr, nullptr, 0);
}